// round 2
// baseline (speedup 1.0000x reference)
#include <cuda_runtime.h>
#include <cuda_fp16.h>
#include <cstdint>

// ============================================================================
// Portable PTX helpers (no 'a'-gated instructions: mma.sync / ldmatrix / cp.async)
// ============================================================================

__device__ __forceinline__ uint32_t smem_to_u32(const void* smem_ptr) {
    uint32_t addr;
    asm("{ .reg .u64 tmp; cvta.to.shared.u64 tmp, %1; cvt.u32.u64 %0, tmp; }"
        : "=r"(addr) : "l"(smem_ptr));
    return addr;
}

__device__ __forceinline__ void cp_async16(uint32_t dst, const void* src) {
    asm volatile("cp.async.cg.shared.global [%0], [%1], 16;"
                 :: "r"(dst), "l"(__cvta_generic_to_global(src)));
}
__device__ __forceinline__ void cp_commit() {
    asm volatile("cp.async.commit_group;" ::: "memory");
}
__device__ __forceinline__ void cp_wait0() {
    asm volatile("cp.async.wait_group 0;" ::: "memory");
}

__device__ __forceinline__ void ldmx4(uint32_t* r, uint32_t addr) {
    asm volatile("ldmatrix.sync.aligned.m8n8.x4.shared.b16 {%0,%1,%2,%3}, [%4];"
                 : "=r"(r[0]), "=r"(r[1]), "=r"(r[2]), "=r"(r[3]) : "r"(addr));
}

__device__ __forceinline__ void mma16816(float* c, const uint32_t* a, const uint32_t* b) {
    asm volatile(
        "mma.sync.aligned.m16n8k16.row.col.f32.f16.f16.f32 "
        "{%0,%1,%2,%3}, {%4,%5,%6,%7}, {%8,%9}, {%0,%1,%2,%3};"
        : "+f"(c[0]), "+f"(c[1]), "+f"(c[2]), "+f"(c[3])
        : "r"(a[0]), "r"(a[1]), "r"(a[2]), "r"(a[3]), "r"(b[0]), "r"(b[1]));
}

// ============================================================================
// Problem constants
// ============================================================================
static constexpr int DIN = 256;    // K
static constexpr int BM  = 128;    // CTA M tile
static constexpr int BN  = 128;    // CTA N tile
static constexpr int BK  = 32;     // K chunk (2 k16 steps)
static constexpr int NCHUNK = DIN / BK;  // 8

// smem strides (bytes), padded for conflict-free ldmatrix / float4
static constexpr int XR_STRIDE = 144;   // 32 fp32 (128B) + 16B pad, 16B-aligned
static constexpr int OP_STRIDE = 80;    // 32 fp16 (64B) + 16B pad, 16B-aligned

// smem layout (dynamic)
static constexpr int SM_XRAW = 0;                        // 2 * 128*144 = 36864
static constexpr int SM_BST  = 36864;                    // 2 * 128*80  = 20480
static constexpr int SM_AHI  = 57344;                    // 128*80 = 10240
static constexpr int SM_ALO  = 67584;                    // 10240
static constexpr int SMEM_SZ = 77824;

// ============================================================================
// Device scratch (no allocation allowed -> __device__ globals)
// ============================================================================
__device__ float  g_gate[8];
__device__ float  g_bias[512];           // [0:256) combined bias c1, [256:512) out bias c2
__device__ float  g_W1[256 * 256];
__device__ __half g_Bh[512 * 256];       // fused weight, [n][k] row-major, fp16

// ============================================================================
// Prep kernels (tiny, fp32)
// ============================================================================

__global__ void prep_gate(const float* __restrict__ pre, const float* __restrict__ post,
                          float* __restrict__ out_tail) {
    int k = threadIdx.x;
    if (k < 8) {
        const float* pr = pre + k * 256;
        const float* po = post + k * 32;
        float sp = 0.f, sq = 0.f;
        for (int i = 0; i < 32; i++) { float a = pr[i], b = po[i]; sp += a * a; sq += b * b; }
        float np = fmaxf(sqrtf(sp), 1e-12f);
        float nq = fmaxf(sqrtf(sq), 1e-12f);
        float d = 0.f;
        for (int i = 0; i < 32; i++) d += (pr[i] / np) * (po[i] / nq);
        float align = 1.0f / (1.0f + expf(-d));
        float g = (align >= 0.3f) ? align : 0.0f;
        g_gate[k] = g;
        out_tail[k] = g;          // alignments
        out_tail[8 + k] = 1.0f;   // allocation_mask
    }
}

// W1 = (gate ⊙ Wc) @ Wp ; c1 = (gate ⊙ Wc) @ bp
__global__ void prep_w1(const float* __restrict__ Wc, const float* __restrict__ Wp,
                        const float* __restrict__ bp) {
    __shared__ float sW[8][256];
    int o0 = blockIdx.x * 8;
    int tid = threadIdx.x;
    for (int r = 0; r < 8; ++r)
        sW[r][tid] = Wc[(o0 + r) * 256 + tid] * g_gate[(o0 + r) >> 5];
    __syncthreads();
    float acc[8] = {0.f, 0.f, 0.f, 0.f, 0.f, 0.f, 0.f, 0.f};
    for (int j = 0; j < 256; ++j) {
        float w = Wp[j * 256 + tid];
#pragma unroll
        for (int r = 0; r < 8; ++r) acc[r] += sW[r][j] * w;
    }
    for (int r = 0; r < 8; ++r) {
        int o = o0 + r;
        g_W1[o * 256 + tid] = acc[r];
        g_Bh[o * 256 + tid] = __float2half_rn(acc[r]);
    }
    if (tid < 8) {
        float c = 0.f;
        for (int j = 0; j < 256; ++j) c += sW[tid][j] * bp[j];
        g_bias[o0 + tid] = c;
    }
}

// W2 = Wo @ W1 ; c2 = Wo @ c1 + bo
__global__ void prep_w2(const float* __restrict__ Wo, const float* __restrict__ bo) {
    __shared__ float sW[8][256];
    int o0 = blockIdx.x * 8;
    int tid = threadIdx.x;
    for (int r = 0; r < 8; ++r)
        sW[r][tid] = Wo[(o0 + r) * 256 + tid];
    __syncthreads();
    float acc[8] = {0.f, 0.f, 0.f, 0.f, 0.f, 0.f, 0.f, 0.f};
    for (int j = 0; j < 256; ++j) {
        float w = g_W1[j * 256 + tid];
#pragma unroll
        for (int r = 0; r < 8; ++r) acc[r] += sW[r][j] * w;
    }
    for (int r = 0; r < 8; ++r)
        g_Bh[(256 + o0 + r) * 256 + tid] = __float2half_rn(acc[r]);
    if (tid < 8) {
        float c = 0.f;
        for (int j = 0; j < 256; ++j) c += sW[tid][j] * g_bias[j];
        g_bias[256 + o0 + tid] = c + bo[o0 + tid];
    }
}

// ============================================================================
// Main fused GEMM: C[131072 x 512] = x[131072 x 256] @ B^T, fp16 2-pass
// (x split hi/lo fp16, W single fp16), HMMA m16n8k16, fp32 accumulate.
// CTA: 128x128, 8 warps (2M x 4N), K chunks of 32, cp.async prefetch depth 1.
// ============================================================================
__global__ void __launch_bounds__(256, 2)
fused_main(const float* __restrict__ x, float* __restrict__ out, int Brows) {
    extern __shared__ char smem[];
    const uint32_t sb = smem_to_u32(smem);
    const int tid  = threadIdx.x;
    const int wid  = tid >> 5, lane = tid & 31;
    const int nt   = blockIdx.x & 3;        // N-tile (0,1: combined; 2,3: out)
    const int mt   = blockIdx.x >> 2;       // M-tile
    const int wm   = wid & 1;               // 2 M-warps of 64 rows
    const int wn   = wid >> 1;              // 4 N-warps of 32 cols

    const float* xbase = x + (size_t)mt * BM * DIN;
    const __half* Bg   = g_Bh + (size_t)nt * BN * DIN;

    float acc[4][4][4];
#pragma unroll
    for (int m = 0; m < 4; m++)
#pragma unroll
        for (int n = 0; n < 4; n++)
#pragma unroll
            for (int k = 0; k < 4; k++) acc[m][n][k] = 0.f;

    auto load_chunk = [&](int c, int s) {
        // x raw fp32: 128 rows x 32 cols = 1024 x 16B segs -> 4/thread
        uint32_t xd = sb + SM_XRAW + s * (BM * XR_STRIDE);
#pragma unroll
        for (int j = 0; j < 4; ++j) {
            int idx = tid * 4 + j;
            int row = idx >> 3, seg = idx & 7;
            cp_async16(xd + row * XR_STRIDE + seg * 16,
                       xbase + row * DIN + c * BK + seg * 4);
        }
        // B fp16: 128 rows x 32 cols = 512 x 16B segs -> 2/thread
        uint32_t bd = sb + SM_BST + s * (BN * OP_STRIDE);
#pragma unroll
        for (int j = 0; j < 2; ++j) {
            int idx = tid * 2 + j;
            int row = idx >> 2, seg = idx & 3;
            cp_async16(bd + row * OP_STRIDE + seg * 16,
                       Bg + row * DIN + c * BK + seg * 8);
        }
        cp_commit();
    };

    load_chunk(0, 0);

#pragma unroll 1
    for (int c = 0; c < NCHUNK; ++c) {
        const int s = c & 1;
        cp_wait0();
        __syncthreads();                       // chunk c resident; prior mma done
        if (c + 1 < NCHUNK) load_chunk(c + 1, s ^ 1);

        // ---- convert fp32 -> fp16 hi/lo into single-buffered A operand ----
        {
            const char* xs = smem + SM_XRAW + s * (BM * XR_STRIDE);
#pragma unroll
            for (int j = 0; j < 4; ++j) {
                int idx = tid * 4 + j;
                int row = idx >> 3, seg = idx & 7;
                float4 v = *(const float4*)(xs + row * XR_STRIDE + seg * 16);
                __half h0 = __float2half_rn(v.x), h1 = __float2half_rn(v.y);
                __half h2 = __float2half_rn(v.z), h3 = __float2half_rn(v.w);
                __half l0 = __float2half_rn(v.x - __half2float(h0));
                __half l1 = __float2half_rn(v.y - __half2float(h1));
                __half l2 = __float2half_rn(v.z - __half2float(h2));
                __half l3 = __float2half_rn(v.w - __half2float(h3));
                uint2 hp, lp;
                hp.x = (uint32_t)__half_as_ushort(h0) | ((uint32_t)__half_as_ushort(h1) << 16);
                hp.y = (uint32_t)__half_as_ushort(h2) | ((uint32_t)__half_as_ushort(h3) << 16);
                lp.x = (uint32_t)__half_as_ushort(l0) | ((uint32_t)__half_as_ushort(l1) << 16);
                lp.y = (uint32_t)__half_as_ushort(l2) | ((uint32_t)__half_as_ushort(l3) << 16);
                *(uint2*)(smem + SM_AHI + row * OP_STRIDE + seg * 8) = hp;
                *(uint2*)(smem + SM_ALO + row * OP_STRIDE + seg * 8) = lp;
            }
        }
        __syncthreads();

        // ---- 2 k16 steps of MMA ----
        const uint32_t bbase = sb + SM_BST + s * (BN * OP_STRIDE);
        const int arow  = wm * 64 + (lane & 15);
        const int brow0 = wn * 32 + ((lane & 7) | ((lane >> 4) << 3));
        const uint32_t acolb = ((lane >> 4) & 1) * 16;
        const uint32_t bcolb = ((lane >> 3) & 1) * 16;
#pragma unroll
        for (int ks = 0; ks < 2; ++ks) {
            uint32_t ahi[4][4], alo[4][4], bf[2][4];
#pragma unroll
            for (int m = 0; m < 4; ++m) {
                uint32_t ra = (uint32_t)((arow + m * 16) * OP_STRIDE) + acolb + ks * 32;
                ldmx4(ahi[m], sb + SM_AHI + ra);
                ldmx4(alo[m], sb + SM_ALO + ra);
            }
#pragma unroll
            for (int p = 0; p < 2; ++p)
                ldmx4(bf[p], bbase + (uint32_t)((brow0 + p * 16) * OP_STRIDE) + bcolb + ks * 32);
#pragma unroll
            for (int m = 0; m < 4; ++m)
#pragma unroll
                for (int n = 0; n < 4; ++n) {
                    const uint32_t* b = &bf[n >> 1][(n & 1) * 2];
                    mma16816(acc[m][n], ahi[m], b);
                    mma16816(acc[m][n], alo[m], b);
                }
        }
    }

    // ---- epilogue: add fused bias, scatter to (out | combined) halves ----
    const int nglob0 = nt * BN + wn * 32;
#pragma unroll
    for (int m = 0; m < 4; ++m) {
        const int row = mt * BM + wm * 64 + m * 16 + (lane >> 2);
#pragma unroll
        for (int n = 0; n < 4; ++n) {
            const int gn = nglob0 + n * 8 + (lane & 3) * 2;
            const float b0 = g_bias[gn], b1 = g_bias[gn + 1];
            float* dst;
            if (gn < 256) dst = out + (size_t)Brows * 256 + (size_t)row * 256 + gn;
            else          dst = out + (size_t)row * 256 + (gn - 256);
            float2 v0 = make_float2(acc[m][n][0] + b0, acc[m][n][1] + b1);
            float2 v1 = make_float2(acc[m][n][2] + b0, acc[m][n][3] + b1);
            *(float2*)dst = v0;
            *(float2*)(dst + 8 * 256) = v1;   // row + 8
        }
    }
}

// ============================================================================
// kernel_launch
// ============================================================================
extern "C" void kernel_launch(void* const* d_in, const int* in_sizes, int n_in,
                              void* d_out, int out_size) {
    const float* x    = (const float*)d_in[0];
    const float* Wp   = (const float*)d_in[1];
    const float* bp   = (const float*)d_in[2];
    const float* pre  = (const float*)d_in[3];
    const float* post = (const float*)d_in[4];
    const float* Wc   = (const float*)d_in[5];
    const float* Wo   = (const float*)d_in[6];
    const float* bo   = (const float*)d_in[7];
    float* out = (float*)d_out;
    const int Brows = in_sizes[0] / 256;   // 131072

    cudaFuncSetAttribute(fused_main, cudaFuncAttributeMaxDynamicSharedMemorySize, SMEM_SZ);

    prep_gate<<<1, 32>>>(pre, post, out + (size_t)2 * Brows * 256);
    prep_w1<<<32, 256>>>(Wc, Wp, bp);
    prep_w2<<<32, 256>>>(Wo, bo);
    fused_main<<<(Brows / BM) * 4, 256, SMEM_SZ>>>(x, out, Brows);
}

// round 3
// speedup vs baseline: 1.5044x; 1.5044x over previous
#include <cuda_runtime.h>
#include <cuda_fp16.h>
#include <cstdint>

// ============================================================================
// Portable PTX helpers (mma.sync / ldmatrix / cp.async only — no 'a'-gated ops)
// ============================================================================

__device__ __forceinline__ uint32_t smem_to_u32(const void* smem_ptr) {
    uint32_t addr;
    asm("{ .reg .u64 tmp; cvta.to.shared.u64 tmp, %1; cvt.u32.u64 %0, tmp; }"
        : "=r"(addr) : "l"(smem_ptr));
    return addr;
}

__device__ __forceinline__ void cp_async16(uint32_t dst, const void* src) {
    asm volatile("cp.async.cg.shared.global [%0], [%1], 16;"
                 :: "r"(dst), "l"(__cvta_generic_to_global(src)));
}
__device__ __forceinline__ void cp_commit() {
    asm volatile("cp.async.commit_group;" ::: "memory");
}
__device__ __forceinline__ void cp_wait0() {
    asm volatile("cp.async.wait_group 0;" ::: "memory");
}

__device__ __forceinline__ void ldmx4(uint32_t* r, uint32_t addr) {
    asm volatile("ldmatrix.sync.aligned.m8n8.x4.shared.b16 {%0,%1,%2,%3}, [%4];"
                 : "=r"(r[0]), "=r"(r[1]), "=r"(r[2]), "=r"(r[3]) : "r"(addr));
}

__device__ __forceinline__ void mma16816(float* c, const uint32_t* a, const uint32_t* b) {
    asm volatile(
        "mma.sync.aligned.m16n8k16.row.col.f32.f16.f16.f32 "
        "{%0,%1,%2,%3}, {%4,%5,%6,%7}, {%8,%9}, {%0,%1,%2,%3};"
        : "+f"(c[0]), "+f"(c[1]), "+f"(c[2]), "+f"(c[3])
        : "r"(a[0]), "r"(a[1]), "r"(a[2]), "r"(a[3]), "r"(b[0]), "r"(b[1]));
}

// ============================================================================
// Problem constants
// ============================================================================
static constexpr int DIN = 256;    // K
static constexpr int BM  = 128;    // CTA M tile
static constexpr int BN  = 128;    // CTA N tile
static constexpr int BK  = 32;     // K chunk (2 k16 steps)
static constexpr int NCHUNK = DIN / BK;  // 8

static constexpr int A_STRIDE = 80;    // 32 fp16 (64B) + 16B pad -> conflict-free ldmatrix
static constexpr int B_STRIDE = 528;   // 256 fp16 (512B) + 16B pad -> conflict-free ldmatrix

// smem layout (dynamic, bytes)
static constexpr int SM_B    = 0;                         // 128 * 528 = 67584 (persistent, full K)
static constexpr int SM_A    = 67584;                     // 2 stages * 128*80 = 20480
static constexpr int SM_BIAS = 88064;                     // 128 floats = 512
static constexpr int SMEM_SZ = 88576;

// ============================================================================
// Device scratch (no allocation allowed -> __device__ globals)
// ============================================================================
__device__ float  g_bias[512];           // [0:256) combined bias c1, [256:512) out bias c2
__device__ float  g_W1[256 * 256];
__device__ __half g_Bh[512 * 256];       // fused weight, [n][k] row-major, fp16

// ============================================================================
// Prep kernels (tiny, fp32).  prep_w1 also computes gates + writes tail outputs.
// ============================================================================

// W1 = (gate ⊙ Wc) @ Wp ; c1 = (gate ⊙ Wc) @ bp ; gates computed per-block (cheap).
__global__ void prep_w1(const float* __restrict__ Wc, const float* __restrict__ Wp,
                        const float* __restrict__ bp,
                        const float* __restrict__ pre, const float* __restrict__ post,
                        float* __restrict__ out_tail) {
    __shared__ float sW[8][256];
    __shared__ float sGate[8];
    int o0 = blockIdx.x * 8;
    int tid = threadIdx.x;
    if (tid < 8) {
        const float* pr = pre + tid * 256;
        const float* po = post + tid * 32;
        float sp = 0.f, sq = 0.f;
        for (int i = 0; i < 32; i++) { float a = pr[i], b = po[i]; sp += a * a; sq += b * b; }
        float np = fmaxf(sqrtf(sp), 1e-12f);
        float nq = fmaxf(sqrtf(sq), 1e-12f);
        float d = 0.f;
        for (int i = 0; i < 32; i++) d += (pr[i] / np) * (po[i] / nq);
        float align = 1.0f / (1.0f + expf(-d));
        float g = (align >= 0.3f) ? align : 0.0f;
        sGate[tid] = g;
        if (blockIdx.x == 0) {
            out_tail[tid] = g;          // alignments
            out_tail[8 + tid] = 1.0f;   // allocation_mask
        }
    }
    __syncthreads();
    for (int r = 0; r < 8; ++r)
        sW[r][tid] = Wc[(o0 + r) * 256 + tid] * sGate[(o0 + r) >> 5];
    __syncthreads();
    float acc[8] = {0.f, 0.f, 0.f, 0.f, 0.f, 0.f, 0.f, 0.f};
    for (int j = 0; j < 256; ++j) {
        float w = Wp[j * 256 + tid];
#pragma unroll
        for (int r = 0; r < 8; ++r) acc[r] += sW[r][j] * w;
    }
    for (int r = 0; r < 8; ++r) {
        int o = o0 + r;
        g_W1[o * 256 + tid] = acc[r];
        g_Bh[o * 256 + tid] = __float2half_rn(acc[r]);
    }
    if (tid < 8) {
        float c = 0.f;
        for (int j = 0; j < 256; ++j) c += sW[tid][j] * bp[j];
        g_bias[o0 + tid] = c;
    }
}

// W2 = Wo @ W1 ; c2 = Wo @ c1 + bo
__global__ void prep_w2(const float* __restrict__ Wo, const float* __restrict__ bo) {
    __shared__ float sW[8][256];
    int o0 = blockIdx.x * 8;
    int tid = threadIdx.x;
    for (int r = 0; r < 8; ++r)
        sW[r][tid] = Wo[(o0 + r) * 256 + tid];
    __syncthreads();
    float acc[8] = {0.f, 0.f, 0.f, 0.f, 0.f, 0.f, 0.f, 0.f};
    for (int j = 0; j < 256; ++j) {
        float w = g_W1[j * 256 + tid];
#pragma unroll
        for (int r = 0; r < 8; ++r) acc[r] += sW[r][j] * w;
    }
    for (int r = 0; r < 8; ++r)
        g_Bh[(256 + o0 + r) * 256 + tid] = __float2half_rn(acc[r]);
    if (tid < 8) {
        float c = 0.f;
        for (int j = 0; j < 256; ++j) c += sW[tid][j] * g_bias[j];
        g_bias[256 + o0 + tid] = c + bo[o0 + tid];
    }
}

// ============================================================================
// Main fused GEMM: C[131072 x 512] = x[131072 x 256] @ B^T, single fp16 pass,
// HMMA m16n8k16, fp32 accumulate.
// CTA: 128x128, 8 warps (2M x 4N). B persistent in smem (full K). A: LDG->regs
// -> fp16 convert -> STS (double-buffered chunks of K=32). 1 sync per chunk.
// ============================================================================
__global__ void __launch_bounds__(256, 2)
fused_main(const float* __restrict__ x, float* __restrict__ out, int Brows) {
    extern __shared__ char smem[];
    const uint32_t sb = smem_to_u32(smem);
    const int tid  = threadIdx.x;
    const int wid  = tid >> 5, lane = tid & 31;
    const int nt   = blockIdx.x & 3;        // N-tile (0,1: combined cols; 2,3: out cols)
    const int mt   = blockIdx.x >> 2;       // M-tile
    const int wm   = wid & 1;               // 2 M-warps of 64 rows
    const int wn   = wid >> 1;              // 4 N-warps of 32 cols

    const float*  xbase = x + (size_t)mt * BM * DIN;
    const __half* Bg    = g_Bh + (size_t)nt * BN * DIN;

    // ---- persistent B tile (full K) + bias via cp.async ----
    {
        const uint32_t bd = sb + SM_B;
#pragma unroll
        for (int i = 0; i < 16; ++i) {
            int idx = tid + 256 * i;            // 4096 x 16B
            int row = idx >> 5, kseg = idx & 31;
            cp_async16(bd + row * B_STRIDE + kseg * 16, Bg + row * DIN + kseg * 8);
        }
        if (tid < 32)
            cp_async16(sb + SM_BIAS + tid * 16, g_bias + nt * BN + tid * 4);
        cp_commit();
    }

    float acc[4][4][4];
#pragma unroll
    for (int m = 0; m < 4; m++)
#pragma unroll
        for (int n = 0; n < 4; n++)
#pragma unroll
            for (int k = 0; k < 4; k++) acc[m][n][k] = 0.f;

    // per-thread x prefetch mapping: idx = tid*4+j -> row = idx>>3, seg = idx&7
    const int prow = tid >> 1;                   // 4 float4 of one row: tid*4/8
    const int pseg0 = (tid & 1) * 4;             // segs 0..3 or 4..7
    float4 pre[4];
#pragma unroll
    for (int j = 0; j < 4; ++j)
        pre[j] = *(const float4*)(xbase + prow * DIN + 0 * BK + (pseg0 + j) * 4);

    const int arow  = wm * 64 + (lane & 15);
    const uint32_t acolb = ((lane >> 4) & 1) * 16;
    const int brow0 = wn * 32 + ((lane & 7) | ((lane >> 4) << 3));
    const uint32_t bcolb = ((lane >> 3) & 1) * 16;

#pragma unroll 1
    for (int c = 0; c < NCHUNK; ++c) {
        const int s = c & 1;

        // ---- convert prefetched fp32 -> fp16, STS to A stage s ----
        {
            char* As = smem + SM_A + s * (BM * A_STRIDE);
#pragma unroll
            for (int j = 0; j < 4; ++j) {
                __half h0 = __float2half_rn(pre[j].x), h1 = __float2half_rn(pre[j].y);
                __half h2 = __float2half_rn(pre[j].z), h3 = __float2half_rn(pre[j].w);
                uint2 hp;
                hp.x = (uint32_t)__half_as_ushort(h0) | ((uint32_t)__half_as_ushort(h1) << 16);
                hp.y = (uint32_t)__half_as_ushort(h2) | ((uint32_t)__half_as_ushort(h3) << 16);
                *(uint2*)(As + prow * A_STRIDE + (pseg0 + j) * 8) = hp;
            }
        }
        if (c == 0) cp_wait0();     // B + bias resident before first ldmatrix
        __syncthreads();

        // ---- prefetch next chunk (LDG in flight under the MMAs) ----
        if (c + 1 < NCHUNK) {
#pragma unroll
            for (int j = 0; j < 4; ++j)
                pre[j] = *(const float4*)(xbase + prow * DIN + (c + 1) * BK + (pseg0 + j) * 4);
        }

        // ---- 2 k16 steps of MMA ----
        const uint32_t abase = sb + SM_A + s * (BM * A_STRIDE);
        const uint32_t bks   = sb + SM_B + (uint32_t)(c * 64);   // c*32 halves = c*64 bytes
#pragma unroll
        for (int ks = 0; ks < 2; ++ks) {
            uint32_t af[4][4], bf[2][4];
#pragma unroll
            for (int m = 0; m < 4; ++m)
                ldmx4(af[m], abase + (uint32_t)((arow + m * 16) * A_STRIDE) + acolb + ks * 32);
#pragma unroll
            for (int p = 0; p < 2; ++p)
                ldmx4(bf[p], bks + (uint32_t)((brow0 + p * 16) * B_STRIDE) + bcolb + ks * 32);
#pragma unroll
            for (int m = 0; m < 4; ++m)
#pragma unroll
                for (int n = 0; n < 4; ++n)
                    mma16816(acc[m][n], af[m], &bf[n >> 1][(n & 1) * 2]);
        }
    }

    // ---- epilogue: add fused bias (smem), scatter to (combined | out) halves ----
    const float* bias_s = (const float*)(smem + SM_BIAS);
#pragma unroll
    for (int m = 0; m < 4; ++m) {
        const int row = mt * BM + wm * 64 + m * 16 + (lane >> 2);
#pragma unroll
        for (int n = 0; n < 4; ++n) {
            const int ln = wn * 32 + n * 8 + (lane & 3) * 2;   // 0..127 within N-tile
            const int gn = nt * BN + ln;                        // 0..511 global col
            const float b0 = bias_s[ln], b1 = bias_s[ln + 1];
            float* dst;
            if (gn < 256) dst = out + (size_t)Brows * 256 + (size_t)row * 256 + gn;
            else          dst = out + (size_t)row * 256 + (gn - 256);
            *(float2*)dst             = make_float2(acc[m][n][0] + b0, acc[m][n][1] + b1);
            *(float2*)(dst + 8 * 256) = make_float2(acc[m][n][2] + b0, acc[m][n][3] + b1);
        }
    }
}

// ============================================================================
// kernel_launch
// ============================================================================
extern "C" void kernel_launch(void* const* d_in, const int* in_sizes, int n_in,
                              void* d_out, int out_size) {
    const float* x    = (const float*)d_in[0];
    const float* Wp   = (const float*)d_in[1];
    const float* bp   = (const float*)d_in[2];
    const float* pre  = (const float*)d_in[3];
    const float* post = (const float*)d_in[4];
    const float* Wc   = (const float*)d_in[5];
    const float* Wo   = (const float*)d_in[6];
    const float* bo   = (const float*)d_in[7];
    float* out = (float*)d_out;
    const int Brows = in_sizes[0] / 256;   // 131072

    cudaFuncSetAttribute(fused_main, cudaFuncAttributeMaxDynamicSharedMemorySize, SMEM_SZ);

    prep_w1<<<32, 256>>>(Wc, Wp, bp, pre, post, out + (size_t)2 * Brows * 256);
    prep_w2<<<32, 256>>>(Wo, bo);
    fused_main<<<(Brows / BM) * 4, 256, SMEM_SZ>>>(x, out, Brows);
}

// round 4
// speedup vs baseline: 1.7332x; 1.1521x over previous
#include <cuda_runtime.h>
#include <cuda_fp16.h>
#include <cstdint>

// ============================================================================
// Portable PTX helpers (mma.sync / ldmatrix / cp.async only — no 'a'-gated ops)
// ============================================================================

__device__ __forceinline__ uint32_t smem_to_u32(const void* smem_ptr) {
    uint32_t addr;
    asm("{ .reg .u64 tmp; cvta.to.shared.u64 tmp, %1; cvt.u32.u64 %0, tmp; }"
        : "=r"(addr) : "l"(smem_ptr));
    return addr;
}

__device__ __forceinline__ void cp_async16(uint32_t dst, const void* src) {
    asm volatile("cp.async.cg.shared.global [%0], [%1], 16;"
                 :: "r"(dst), "l"(__cvta_generic_to_global(src)));
}
__device__ __forceinline__ void cp_commit() {
    asm volatile("cp.async.commit_group;" ::: "memory");
}
__device__ __forceinline__ void cp_wait0() {
    asm volatile("cp.async.wait_group 0;" ::: "memory");
}

__device__ __forceinline__ void ldmx4(uint32_t* r, uint32_t addr) {
    asm volatile("ldmatrix.sync.aligned.m8n8.x4.shared.b16 {%0,%1,%2,%3}, [%4];"
                 : "=r"(r[0]), "=r"(r[1]), "=r"(r[2]), "=r"(r[3]) : "r"(addr));
}

__device__ __forceinline__ void mma16816(float* c, const uint32_t* a, const uint32_t* b) {
    asm volatile(
        "mma.sync.aligned.m16n8k16.row.col.f32.f16.f16.f32 "
        "{%0,%1,%2,%3}, {%4,%5,%6,%7}, {%8,%9}, {%0,%1,%2,%3};"
        : "+f"(c[0]), "+f"(c[1]), "+f"(c[2]), "+f"(c[3])
        : "r"(a[0]), "r"(a[1]), "r"(a[2]), "r"(a[3]), "r"(b[0]), "r"(b[1]));
}

// ============================================================================
// Problem constants
// ============================================================================
static constexpr int DIN = 256;    // K
static constexpr int BM  = 128;    // CTA M tile
static constexpr int BN  = 128;    // CTA N tile
static constexpr int BK  = 32;     // K chunk (2 k16 steps)
static constexpr int NCHUNK = DIN / BK;  // 8

static constexpr int A_STRIDE = 80;    // 32 fp16 (64B) + 16B pad -> conflict-free ldmatrix
static constexpr int B_STRIDE = 528;   // 256 fp16 (512B) + 16B pad -> conflict-free ldmatrix

// smem layout (dynamic, bytes)
static constexpr int SM_B    = 0;                         // 128 * 528 = 67584 (persistent, full K)
static constexpr int SM_A    = 67584;                     // 2 stages * 128*80 = 20480
static constexpr int SM_BIAS = 88064;                     // 128 floats = 512
static constexpr int SMEM_SZ = 88576;

// ============================================================================
// Device scratch (no allocation allowed -> __device__ globals)
// ============================================================================
__device__ float  g_bias[512];           // [0:256) combined bias c1, [256:512) out bias c2
__device__ float  g_W1[256 * 256];
__device__ __half g_Bh[512 * 256];       // fused weight, [n][k] row-major, fp16

// ============================================================================
// Prep kernels: one output row per block, grid 256 x block 256.
// ============================================================================

__device__ __forceinline__ float warp_sum(float v) {
#pragma unroll
    for (int o = 16; o > 0; o >>= 1) v += __shfl_xor_sync(0xffffffffu, v, o);
    return v;
}

// Block o computes W1[o,:] = sum_i (gate[o/32] * Wc[o,i]) * Wp[i,:]
// and c1[o] = sum_i (gate*Wc[o,i]) * bp[i].
__global__ void __launch_bounds__(256, 4)
prep_w1(const float* __restrict__ Wc, const float* __restrict__ Wp,
        const float* __restrict__ bp,
        const float* __restrict__ pre, const float* __restrict__ post,
        float* __restrict__ out_tail) {
    __shared__ float sWc[256];
    __shared__ float sRed[8];
    __shared__ float sGate;
    const int o = blockIdx.x;
    const int tid = threadIdx.x;
    const int ko = o >> 5;

    // gate for nanocolumn ko (warp 0, shuffle reductions over the 32-elem prefix)
    if (tid < 32) {
        float a = pre[ko * 256 + tid];
        float b = post[ko * 32 + tid];
        float sp = warp_sum(a * a);
        float sq = warp_sum(b * b);
        float np = fmaxf(sqrtf(sp), 1e-12f);
        float nq = fmaxf(sqrtf(sq), 1e-12f);
        float d  = warp_sum((a / np) * (b / nq));
        if (tid == 0) {
            float align = 1.0f / (1.0f + expf(-d));
            float g = (align >= 0.3f) ? align : 0.0f;
            sGate = g;
            if ((o & 31) == 0) {
                out_tail[ko] = g;          // alignments
                out_tail[8 + ko] = 1.0f;   // allocation_mask
            }
        }
    }
    __syncthreads();
    const float g = sGate;
    sWc[tid] = Wc[o * 256 + tid] * g;
    __syncthreads();

    float acc = 0.f;
#pragma unroll 8
    for (int i = 0; i < 256; ++i)
        acc += sWc[i] * Wp[i * 256 + tid];
    g_W1[o * 256 + tid] = acc;
    g_Bh[o * 256 + tid] = __float2half_rn(acc);

    // c1[o] = dot(sWc, bp): block reduce
    float p = sWc[tid] * bp[tid];
    p = warp_sum(p);
    if ((tid & 31) == 0) sRed[tid >> 5] = p;
    __syncthreads();
    if (tid == 0) {
        float c = 0.f;
#pragma unroll
        for (int w = 0; w < 8; ++w) c += sRed[w];
        g_bias[o] = c;
    }
}

// Block o computes W2[o,:] = sum_i Wo[o,i] * W1[i,:]
// and c2[o] = dot(Wo[o,:], c1) + bo[o].
__global__ void __launch_bounds__(256, 4)
prep_w2(const float* __restrict__ Wo, const float* __restrict__ bo) {
    __shared__ float sWo[256];
    __shared__ float sRed[8];
    const int o = blockIdx.x;
    const int tid = threadIdx.x;
    sWo[tid] = Wo[o * 256 + tid];
    __syncthreads();

    float acc = 0.f;
#pragma unroll 8
    for (int i = 0; i < 256; ++i)
        acc += sWo[i] * g_W1[i * 256 + tid];
    g_Bh[(256 + o) * 256 + tid] = __float2half_rn(acc);

    float p = sWo[tid] * g_bias[tid];
    p = warp_sum(p);
    if ((tid & 31) == 0) sRed[tid >> 5] = p;
    __syncthreads();
    if (tid == 0) {
        float c = 0.f;
#pragma unroll
        for (int w = 0; w < 8; ++w) c += sRed[w];
        g_bias[256 + o] = c + bo[o];
    }
}

// ============================================================================
// Main fused GEMM: C[131072 x 512] = x[131072 x 256] @ B^T, single fp16 pass,
// HMMA m16n8k16, fp32 accumulate.
// CTA: 128x128, 8 warps (2M x 4N). B persistent in smem (full K). A: LDG->regs
// -> fp16 convert -> STS (double-buffered chunks of K=32). 1 sync per chunk.
// ============================================================================
__global__ void __launch_bounds__(256, 2)
fused_main(const float* __restrict__ x, float* __restrict__ out, int Brows) {
    extern __shared__ char smem[];
    const uint32_t sb = smem_to_u32(smem);
    const int tid  = threadIdx.x;
    const int wid  = tid >> 5, lane = tid & 31;
    const int nt   = blockIdx.x & 3;        // N-tile (0,1: combined cols; 2,3: out cols)
    const int mt   = blockIdx.x >> 2;       // M-tile
    const int wm   = wid & 1;               // 2 M-warps of 64 rows
    const int wn   = wid >> 1;              // 4 N-warps of 32 cols

    const float*  xbase = x + (size_t)mt * BM * DIN;
    const __half* Bg    = g_Bh + (size_t)nt * BN * DIN;

    // ---- persistent B tile (full K) + bias via cp.async ----
    {
        const uint32_t bd = sb + SM_B;
#pragma unroll
        for (int i = 0; i < 16; ++i) {
            int idx = tid + 256 * i;            // 4096 x 16B
            int row = idx >> 5, kseg = idx & 31;
            cp_async16(bd + row * B_STRIDE + kseg * 16, Bg + row * DIN + kseg * 8);
        }
        if (tid < 32)
            cp_async16(sb + SM_BIAS + tid * 16, g_bias + nt * BN + tid * 4);
        cp_commit();
    }

    float acc[4][4][4];
#pragma unroll
    for (int m = 0; m < 4; m++)
#pragma unroll
        for (int n = 0; n < 4; n++)
#pragma unroll
            for (int k = 0; k < 4; k++) acc[m][n][k] = 0.f;

    // per-thread x prefetch mapping
    const int prow = tid >> 1;                   // row 0..127
    const int pseg0 = (tid & 1) * 4;             // segs 0..3 or 4..7
    float4 pre[4];
#pragma unroll
    for (int j = 0; j < 4; ++j)
        pre[j] = *(const float4*)(xbase + prow * DIN + (pseg0 + j) * 4);

    const int arow  = wm * 64 + (lane & 15);
    const uint32_t acolb = ((lane >> 4) & 1) * 16;
    const int brow0 = wn * 32 + ((lane & 7) | ((lane >> 4) << 3));
    const uint32_t bcolb = ((lane >> 3) & 1) * 16;

#pragma unroll 1
    for (int c = 0; c < NCHUNK; ++c) {
        const int s = c & 1;

        // ---- convert prefetched fp32 -> fp16, STS to A stage s ----
        {
            char* As = smem + SM_A + s * (BM * A_STRIDE);
#pragma unroll
            for (int j = 0; j < 4; ++j) {
                __half h0 = __float2half_rn(pre[j].x), h1 = __float2half_rn(pre[j].y);
                __half h2 = __float2half_rn(pre[j].z), h3 = __float2half_rn(pre[j].w);
                uint2 hp;
                hp.x = (uint32_t)__half_as_ushort(h0) | ((uint32_t)__half_as_ushort(h1) << 16);
                hp.y = (uint32_t)__half_as_ushort(h2) | ((uint32_t)__half_as_ushort(h3) << 16);
                *(uint2*)(As + prow * A_STRIDE + (pseg0 + j) * 8) = hp;
            }
        }
        if (c == 0) cp_wait0();     // B + bias resident before first ldmatrix
        __syncthreads();

        // ---- prefetch next chunk (LDG in flight under the MMAs) ----
        if (c + 1 < NCHUNK) {
#pragma unroll
            for (int j = 0; j < 4; ++j)
                pre[j] = *(const float4*)(xbase + prow * DIN + (c + 1) * BK + (pseg0 + j) * 4);
        }

        // ---- 2 k16 steps of MMA ----
        const uint32_t abase = sb + SM_A + s * (BM * A_STRIDE);
        const uint32_t bks   = sb + SM_B + (uint32_t)(c * 64);   // c*32 halves = c*64 bytes
#pragma unroll
        for (int ks = 0; ks < 2; ++ks) {
            uint32_t af[4][4], bf[2][4];
#pragma unroll
            for (int m = 0; m < 4; ++m)
                ldmx4(af[m], abase + (uint32_t)((arow + m * 16) * A_STRIDE) + acolb + ks * 32);
#pragma unroll
            for (int p = 0; p < 2; ++p)
                ldmx4(bf[p], bks + (uint32_t)((brow0 + p * 16) * B_STRIDE) + bcolb + ks * 32);
#pragma unroll
            for (int m = 0; m < 4; ++m)
#pragma unroll
                for (int n = 0; n < 4; ++n)
                    mma16816(acc[m][n], af[m], &bf[n >> 1][(n & 1) * 2]);
        }
    }

    // ---- epilogue: add fused bias (smem), scatter to (combined | out) halves ----
    const float* bias_s = (const float*)(smem + SM_BIAS);
#pragma unroll
    for (int m = 0; m < 4; ++m) {
        const int row = mt * BM + wm * 64 + m * 16 + (lane >> 2);
#pragma unroll
        for (int n = 0; n < 4; ++n) {
            const int ln = wn * 32 + n * 8 + (lane & 3) * 2;   // 0..127 within N-tile
            const int gn = nt * BN + ln;                        // 0..511 global col
            const float b0 = bias_s[ln], b1 = bias_s[ln + 1];
            float* dst;
            if (gn < 256) dst = out + (size_t)Brows * 256 + (size_t)row * 256 + gn;
            else          dst = out + (size_t)row * 256 + (gn - 256);
            *(float2*)dst             = make_float2(acc[m][n][0] + b0, acc[m][n][1] + b1);
            *(float2*)(dst + 8 * 256) = make_float2(acc[m][n][2] + b0, acc[m][n][3] + b1);
        }
    }
}

// ============================================================================
// kernel_launch
// ============================================================================
extern "C" void kernel_launch(void* const* d_in, const int* in_sizes, int n_in,
                              void* d_out, int out_size) {
    const float* x    = (const float*)d_in[0];
    const float* Wp   = (const float*)d_in[1];
    const float* bp   = (const float*)d_in[2];
    const float* pre  = (const float*)d_in[3];
    const float* post = (const float*)d_in[4];
    const float* Wc   = (const float*)d_in[5];
    const float* Wo   = (const float*)d_in[6];
    const float* bo   = (const float*)d_in[7];
    float* out = (float*)d_out;
    const int Brows = in_sizes[0] / 256;   // 131072

    cudaFuncSetAttribute(fused_main, cudaFuncAttributeMaxDynamicSharedMemorySize, SMEM_SZ);

    prep_w1<<<256, 256>>>(Wc, Wp, bp, pre, post, out + (size_t)2 * Brows * 256);
    prep_w2<<<256, 256>>>(Wo, bo);
    fused_main<<<(Brows / BM) * 4, 256, SMEM_SZ>>>(x, out, Brows);
}

// round 5
// speedup vs baseline: 1.8641x; 1.0756x over previous
#include <cuda_runtime.h>
#include <cuda_fp16.h>
#include <cstdint>

// ============================================================================
// Portable PTX helpers (mma.sync / ldmatrix / cp.async only — no 'a'-gated ops)
// ============================================================================

__device__ __forceinline__ uint32_t smem_to_u32(const void* smem_ptr) {
    uint32_t addr;
    asm("{ .reg .u64 tmp; cvta.to.shared.u64 tmp, %1; cvt.u32.u64 %0, tmp; }"
        : "=r"(addr) : "l"(smem_ptr));
    return addr;
}

__device__ __forceinline__ void cp_async16(uint32_t dst, const void* src) {
    asm volatile("cp.async.cg.shared.global [%0], [%1], 16;"
                 :: "r"(dst), "l"(__cvta_generic_to_global(src)));
}
__device__ __forceinline__ void cp_commit() {
    asm volatile("cp.async.commit_group;" ::: "memory");
}
__device__ __forceinline__ void cp_wait0() {
    asm volatile("cp.async.wait_group 0;" ::: "memory");
}

__device__ __forceinline__ void ldmx4(uint32_t* r, uint32_t addr) {
    asm volatile("ldmatrix.sync.aligned.m8n8.x4.shared.b16 {%0,%1,%2,%3}, [%4];"
                 : "=r"(r[0]), "=r"(r[1]), "=r"(r[2]), "=r"(r[3]) : "r"(addr));
}

__device__ __forceinline__ void mma16816(float* c, const uint32_t* a, const uint32_t* b) {
    asm volatile(
        "mma.sync.aligned.m16n8k16.row.col.f32.f16.f16.f32 "
        "{%0,%1,%2,%3}, {%4,%5,%6,%7}, {%8,%9}, {%0,%1,%2,%3};"
        : "+f"(c[0]), "+f"(c[1]), "+f"(c[2]), "+f"(c[3])
        : "r"(a[0]), "r"(a[1]), "r"(a[2]), "r"(a[3]), "r"(b[0]), "r"(b[1]));
}

// ============================================================================
// Problem constants
// ============================================================================
static constexpr int DIN = 256;    // K
static constexpr int BM  = 128;    // CTA M tile
static constexpr int BN  = 256;    // CTA N tile (halves x L2 traffic vs 128)
static constexpr int BK  = 32;     // K chunk (2 k16 steps)
static constexpr int NCHUNK = DIN / BK;  // 8

static constexpr int A_STRIDE = 80;    // 32 fp16 (64B) + 16B pad -> conflict-free ldmatrix
static constexpr int B_STRIDE = 528;   // 256 fp16 (512B) + 16B pad -> conflict-free ldmatrix

// smem layout (dynamic, bytes)
static constexpr int SM_B    = 0;                   // 256 * 528 = 135168 (persistent, full K)
static constexpr int SM_A    = 135168;              // 2 stages * 128*80 = 20480
static constexpr int SM_BIAS = 155648;              // 256 floats = 1024
static constexpr int SMEM_SZ = 156672;

// ============================================================================
// Device scratch (no allocation allowed -> __device__ globals)
// ============================================================================
__device__ float  g_bias[512];           // [0:256) combined bias c1, [256:512) out bias c2
__device__ float  g_W1[256 * 256];
__device__ __half g_Bh[512 * 256];       // fused weight, [n][k] row-major, fp16

// ============================================================================
// Prep kernels: one output row per block, grid 256 x block 256, 4-way ILP.
// ============================================================================

__device__ __forceinline__ float warp_sum(float v) {
#pragma unroll
    for (int o = 16; o > 0; o >>= 1) v += __shfl_xor_sync(0xffffffffu, v, o);
    return v;
}

// Block o computes W1[o,:] = sum_i (gate[o/32] * Wc[o,i]) * Wp[i,:]
// and c1[o] = sum_i (gate*Wc[o,i]) * bp[i].
__global__ void __launch_bounds__(256, 4)
prep_w1(const float* __restrict__ Wc, const float* __restrict__ Wp,
        const float* __restrict__ bp,
        const float* __restrict__ pre, const float* __restrict__ post,
        float* __restrict__ out_tail) {
    __shared__ float sWc[256];
    __shared__ float sRed[8];
    __shared__ float sGate;
    const int o = blockIdx.x;
    const int tid = threadIdx.x;
    const int ko = o >> 5;

    if (tid < 32) {
        float a = pre[ko * 256 + tid];
        float b = post[ko * 32 + tid];
        float sp = warp_sum(a * a);
        float sq = warp_sum(b * b);
        float np = fmaxf(sqrtf(sp), 1e-12f);
        float nq = fmaxf(sqrtf(sq), 1e-12f);
        float d  = warp_sum((a / np) * (b / nq));
        if (tid == 0) {
            float align = 1.0f / (1.0f + expf(-d));
            float g = (align >= 0.3f) ? align : 0.0f;
            sGate = g;
            if ((o & 31) == 0) {
                out_tail[ko] = g;          // alignments
                out_tail[8 + ko] = 1.0f;   // allocation_mask
            }
        }
    }
    __syncthreads();
    const float g = sGate;
    sWc[tid] = Wc[o * 256 + tid] * g;
    __syncthreads();

    float a0 = 0.f, a1 = 0.f, a2 = 0.f, a3 = 0.f;
#pragma unroll 2
    for (int i = 0; i < 256; i += 4) {
        a0 += sWc[i + 0] * Wp[(i + 0) * 256 + tid];
        a1 += sWc[i + 1] * Wp[(i + 1) * 256 + tid];
        a2 += sWc[i + 2] * Wp[(i + 2) * 256 + tid];
        a3 += sWc[i + 3] * Wp[(i + 3) * 256 + tid];
    }
    float acc = (a0 + a1) + (a2 + a3);
    g_W1[o * 256 + tid] = acc;
    g_Bh[o * 256 + tid] = __float2half_rn(acc);

    float p = sWc[tid] * bp[tid];
    p = warp_sum(p);
    if ((tid & 31) == 0) sRed[tid >> 5] = p;
    __syncthreads();
    if (tid == 0) {
        float c = 0.f;
#pragma unroll
        for (int w = 0; w < 8; ++w) c += sRed[w];
        g_bias[o] = c;
    }
}

// Block o computes W2[o,:] = sum_i Wo[o,i] * W1[i,:]
// and c2[o] = dot(Wo[o,:], c1) + bo[o].
__global__ void __launch_bounds__(256, 4)
prep_w2(const float* __restrict__ Wo, const float* __restrict__ bo) {
    __shared__ float sWo[256];
    __shared__ float sRed[8];
    const int o = blockIdx.x;
    const int tid = threadIdx.x;
    sWo[tid] = Wo[o * 256 + tid];
    __syncthreads();

    float a0 = 0.f, a1 = 0.f, a2 = 0.f, a3 = 0.f;
#pragma unroll 2
    for (int i = 0; i < 256; i += 4) {
        a0 += sWo[i + 0] * g_W1[(i + 0) * 256 + tid];
        a1 += sWo[i + 1] * g_W1[(i + 1) * 256 + tid];
        a2 += sWo[i + 2] * g_W1[(i + 2) * 256 + tid];
        a3 += sWo[i + 3] * g_W1[(i + 3) * 256 + tid];
    }
    float acc = (a0 + a1) + (a2 + a3);
    g_Bh[(256 + o) * 256 + tid] = __float2half_rn(acc);

    float p = sWo[tid] * g_bias[tid];
    p = warp_sum(p);
    if ((tid & 31) == 0) sRed[tid >> 5] = p;
    __syncthreads();
    if (tid == 0) {
        float c = 0.f;
#pragma unroll
        for (int w = 0; w < 8; ++w) c += sRed[w];
        g_bias[256 + o] = c + bo[o];
    }
}

// ============================================================================
// Main fused GEMM: C[131072 x 512] = x[131072 x 256] @ B^T, single fp16 pass,
// HMMA m16n8k16, fp32 accumulate.
// CTA: 128x256, 16 warps (4M x 4N, warp tile 32x64), block 512.
// B persistent in smem (full K for this CTA's 256-col half). A: LDG->regs ->
// fp16 convert -> STS (double-buffered K chunks of 32). 1 sync per chunk.
// nt (blockIdx.x & 1) wholly selects combined (0) vs out (1) output half.
// ============================================================================
__global__ void __launch_bounds__(512, 1)
fused_main(const float* __restrict__ x, float* __restrict__ out, int Brows) {
    extern __shared__ char smem[];
    const uint32_t sb = smem_to_u32(smem);
    const int tid  = threadIdx.x;
    const int wid  = tid >> 5, lane = tid & 31;
    const int nt   = blockIdx.x & 1;        // 0: combined cols, 1: out cols
    const int mt   = blockIdx.x >> 1;       // M-tile
    const int wm   = wid & 3;               // 4 M-warps of 32 rows
    const int wn   = wid >> 2;              // 4 N-warps of 64 cols

    const float*  xbase = x + (size_t)mt * BM * DIN;
    const __half* Bg    = g_Bh + (size_t)nt * BN * DIN;

    // ---- persistent B tile (256 rows x full K) + bias via cp.async ----
    {
        const uint32_t bd = sb + SM_B;
#pragma unroll
        for (int i = 0; i < 16; ++i) {
            int idx = tid + 512 * i;            // 8192 x 16B
            int row = idx >> 5, kseg = idx & 31;
            cp_async16(bd + row * B_STRIDE + kseg * 16, Bg + row * DIN + kseg * 8);
        }
        if (tid < 64)
            cp_async16(sb + SM_BIAS + tid * 16, g_bias + nt * BN + tid * 4);
        cp_commit();
    }

    float acc[2][8][4];
#pragma unroll
    for (int m = 0; m < 2; m++)
#pragma unroll
        for (int n = 0; n < 8; n++)
#pragma unroll
            for (int k = 0; k < 4; k++) acc[m][n][k] = 0.f;

    // per-thread x prefetch: 2 float4 per chunk; idx = tid*2+j -> row=idx>>3
    const int prow  = tid >> 2;                  // row 0..127
    const int pseg0 = (tid & 3) * 2;             // segs {0,1},{2,3},{4,5},{6,7}
    float4 pre[2];
#pragma unroll
    for (int j = 0; j < 2; ++j)
        pre[j] = *(const float4*)(xbase + prow * DIN + (pseg0 + j) * 4);

    const int arow  = wm * 32 + (lane & 15);
    const uint32_t acolb = ((lane >> 4) & 1) * 16;
    const int brow0 = wn * 64 + ((lane & 7) | ((lane >> 4) << 3));
    const uint32_t bcolb = ((lane >> 3) & 1) * 16;

#pragma unroll 1
    for (int c = 0; c < NCHUNK; ++c) {
        const int s = c & 1;

        // ---- convert prefetched fp32 -> fp16, STS to A stage s ----
        {
            char* As = smem + SM_A + s * (BM * A_STRIDE);
#pragma unroll
            for (int j = 0; j < 2; ++j) {
                __half h0 = __float2half_rn(pre[j].x), h1 = __float2half_rn(pre[j].y);
                __half h2 = __float2half_rn(pre[j].z), h3 = __float2half_rn(pre[j].w);
                uint2 hp;
                hp.x = (uint32_t)__half_as_ushort(h0) | ((uint32_t)__half_as_ushort(h1) << 16);
                hp.y = (uint32_t)__half_as_ushort(h2) | ((uint32_t)__half_as_ushort(h3) << 16);
                *(uint2*)(As + prow * A_STRIDE + (pseg0 + j) * 8) = hp;
            }
        }
        if (c == 0) cp_wait0();     // B + bias resident before first ldmatrix
        __syncthreads();

        // ---- prefetch next chunk (LDG in flight under the MMAs) ----
        if (c + 1 < NCHUNK) {
#pragma unroll
            for (int j = 0; j < 2; ++j)
                pre[j] = *(const float4*)(xbase + prow * DIN + (c + 1) * BK + (pseg0 + j) * 4);
        }

        // ---- 2 k16 steps of MMA ----
        const uint32_t abase = sb + SM_A + s * (BM * A_STRIDE);
        const uint32_t bks   = sb + SM_B + (uint32_t)(c * 64);   // c*32 halves = c*64 bytes
#pragma unroll
        for (int ks = 0; ks < 2; ++ks) {
            uint32_t af[2][4], bf[4][4];
#pragma unroll
            for (int m = 0; m < 2; ++m)
                ldmx4(af[m], abase + (uint32_t)((arow + m * 16) * A_STRIDE) + acolb + ks * 32);
#pragma unroll
            for (int p = 0; p < 4; ++p)
                ldmx4(bf[p], bks + (uint32_t)((brow0 + p * 16) * B_STRIDE) + bcolb + ks * 32);
#pragma unroll
            for (int m = 0; m < 2; ++m)
#pragma unroll
                for (int n = 0; n < 8; ++n)
                    mma16816(acc[m][n], af[m], &bf[n >> 1][(n & 1) * 2]);
        }
    }

    // ---- epilogue: add fused bias (smem), write this CTA's output half ----
    const float* bias_s = (const float*)(smem + SM_BIAS);
    // nt==0 -> combined block (second Brows*256 of out); nt==1 -> out block (first)
    float* hbase = out + (nt ? (size_t)0 : (size_t)Brows * 256);
#pragma unroll
    for (int m = 0; m < 2; ++m) {
        const int row = mt * BM + wm * 32 + m * 16 + (lane >> 2);
        float* rp = hbase + (size_t)row * 256;
#pragma unroll
        for (int n = 0; n < 8; ++n) {
            const int ln = wn * 64 + n * 8 + (lane & 3) * 2;   // 0..255 column
            const float b0 = bias_s[ln], b1 = bias_s[ln + 1];
            *(float2*)(rp + ln)             = make_float2(acc[m][n][0] + b0, acc[m][n][1] + b1);
            *(float2*)(rp + ln + 8 * 256)   = make_float2(acc[m][n][2] + b0, acc[m][n][3] + b1);
        }
    }
}

// ============================================================================
// kernel_launch
// ============================================================================
extern "C" void kernel_launch(void* const* d_in, const int* in_sizes, int n_in,
                              void* d_out, int out_size) {
    const float* x    = (const float*)d_in[0];
    const float* Wp   = (const float*)d_in[1];
    const float* bp   = (const float*)d_in[2];
    const float* pre  = (const float*)d_in[3];
    const float* post = (const float*)d_in[4];
    const float* Wc   = (const float*)d_in[5];
    const float* Wo   = (const float*)d_in[6];
    const float* bo   = (const float*)d_in[7];
    float* out = (float*)d_out;
    const int Brows = in_sizes[0] / 256;   // 131072

    cudaFuncSetAttribute(fused_main, cudaFuncAttributeMaxDynamicSharedMemorySize, SMEM_SZ);

    prep_w1<<<256, 256>>>(Wc, Wp, bp, pre, post, out + (size_t)2 * Brows * 256);
    prep_w2<<<256, 256>>>(Wo, bo);
    fused_main<<<(Brows / BM) * 2, 512, SMEM_SZ>>>(x, out, Brows);
}